// round 13
// baseline (speedup 1.0000x reference)
#include <cuda_runtime.h>
#include <math.h>

#define EPSF 1e-8f
#define NB 3
#define NF 1024
#define NP 768
#define IMG 128
#define NPIX (IMG * IMG)

#define SC_BLOCKS 768          // 6144 warps = 2 per (layer,face), 8 warps/block
#define SHADE_BLOCKS 64        // last 64 finishers shade 256 pixels each

// out offsets (f32 elements)
#define OFF_IM     0
#define OFF_PROB   49152
#define OFF_NORM   65536
#define OFF_FG     74752

// Combined composite/z buffer, one u64 per pixel. 0 = empty (module-load
// default, restored by the shade phase each call).
// key = rank<<62 | (~bits(z))<<30 | (1023-f)<<20 | layer<<18 | tyi<<9 | txi
static __device__ unsigned long long g_zbuf[NPIX];
// Monotone completion counter (never reset; epoch = value / SC_BLOCKS).
static __device__ unsigned long long g_fin;

__device__ __forceinline__ float pix_x(int x) {
    const float STEP = 2.0f / 127.0f;
    return (x == 127) ? 1.0f : (-1.0f + x * STEP);
}
__device__ __forceinline__ float pix_y(int y) {
    const float STEP = 2.0f / 127.0f;
    return (y == 127) ? -1.0f : (1.0f - y * STEP);
}

// stable argsort of -ts[:,2] over 3 layers; returns rank of layer l (0..2)
__device__ __forceinline__ int layer_rank(const float* ts, int l) {
    float k0 = -ts[2], k1 = -ts[5], k2 = -ts[8];
    int o0 = 0; float kv = k0;
    if (k1 < kv) { o0 = 1; kv = k1; }
    if (k2 < kv) { o0 = 2; kv = k2; }
    int r0i = (o0 == 0) ? 1 : 0;
    int r1i = (o0 == 2) ? 1 : 2;
    float kr0 = (r0i == 0) ? k0 : k1;
    float kr1 = (r1i == 1) ? k1 : k2;
    int o1, o2;
    if (kr0 <= kr1) { o1 = r0i; o2 = r1i; }
    else            { o1 = r1i; o2 = r0i; }
    return (l == o0) ? 0 : ((l == o1) ? 1 : 2);
}

// ---------------------------------------------------------------------------
// Single kernel: prep + scatter, then completion-detected shade by the last
// SHADE_BLOCKS blocks to finish. Two warps per (layer, face), interleaved
// halves of the flattened bbox sweep. All selection/interp math identical to
// the passing R12 kernel.
// ---------------------------------------------------------------------------
__global__ void __launch_bounds__(256)
render_kernel(const float* __restrict__ pts,
              const float* __restrict__ camrot,
              const float* __restrict__ campos,
              const float* __restrict__ proj,
              const int*   __restrict__ faces,
              const float* __restrict__ uv,
              const float* __restrict__ ts,
              const float* __restrict__ tex,
              float* __restrict__ out) {
    // ===================== Phase 1: prep + scatter =====================
    {
        int w = (blockIdx.x * blockDim.x + threadIdx.x) >> 5;   // 0 .. 6143
        int lane = threadIdx.x & 31;
        int wg = w >> 1;            // (layer, face) id
        int half = w & 1;
        int l = wg >> 10;
        int f = wg & (NF - 1);

        int vis[3] = {faces[f * 3 + 0], faces[f * 3 + 1], faces[f * 3 + 2]};
        const float* R = camrot + l * 9;
        const float* C = campos + l * 3;
        float p0 = proj[0], p1 = proj[1];

        float vx[3], vy[3], vz[3], sx[3], sy[3];
#pragma unroll
        for (int k = 0; k < 3; k++) {
            const float* P = pts + (l * NP + vis[k]) * 3;
            float q0 = P[0] - C[0], q1 = P[1] - C[1], q2 = P[2] - C[2];
            float X = R[0] * q0 + R[1] * q1 + R[2] * q2;
            float Y = R[3] * q0 + R[4] * q1 + R[5] * q2;
            float Z = R[6] * q0 + R[7] * q1 + R[8] * q2;
            vx[k] = X; vy[k] = Y; vz[k] = Z;
            float zd = Z + EPSF;
            sx[k] = __fdiv_rn(X * p0, zd);
            sy[k] = __fdiv_rn(Y * p1, zd);
        }

        if (lane == 0 && half == 0) {
            float e1xx = vx[1] - vx[0], e1yy = vy[1] - vy[0], e1zz = vz[1] - vz[0];
            float e2xx = vx[2] - vx[0], e2yy = vy[2] - vy[0], e2zz = vz[2] - vz[0];
            float nx = e1yy * e2zz - e1zz * e2yy;
            float ny = e1zz * e2xx - e1xx * e2zz;
            float nz = e1xx * e2yy - e1yy * e2xx;
            float nn = __fsqrt_rn(nx * nx + ny * ny + nz * nz) + EPSF;
            float* on = out + OFF_NORM + wg * 3;
            on[0] = __fdiv_rn(nx, nn);
            on[1] = __fdiv_rn(ny, nn);
            on[2] = __fdiv_rn(nz, nn);
        }

        float ax = sx[0], ay = sy[0], bx = sx[1], by = sy[1], cx = sx[2], cy = sy[2];
        float d = (by - cy) * (ax - cx) + (cx - bx) * (ay - cy);
        float zmax = fmaxf(vz[0], fmaxf(vz[1], vz[2]));
        bool valid = (fabsf(d) > EPSF) && (zmax > EPSF);

        if (valid) {
            float dn = d + EPSF;
            float rd = __frcp_rn(dn);
            float4 A = make_float4(by - cy, cx - bx, cy - ay, ax - cx);
            float4 B = make_float4(cx, cy, rd, vz[0]);
            float z1v = vz[1], z2v = vz[2];

            const float* U = uv + l * NP * 2;
            float u0 = U[2 * vis[0]],     u1 = U[2 * vis[1]],     u2 = U[2 * vis[2]];
            float v0 = U[2 * vis[0] + 1], v1 = U[2 * vis[1] + 1], v2 = U[2 * vis[2] + 1];

            const float STEP = 2.0f / 127.0f;
            float pad = 1.0f * STEP;
            float xmin = fminf(ax, fminf(bx, cx)) - pad;
            float xmax = fmaxf(ax, fmaxf(bx, cx)) + pad;
            float ymin = fminf(ay, fminf(by, cy)) - pad;
            float ymax = fmaxf(ay, fmaxf(by, cy)) + pad;

            const float INV_STEP = 63.5f;   // 1 / (2/127)
            int x0 = max(0, (int)floorf((xmin + 1.0f) * INV_STEP));
            int x1 = min(IMG - 1, (int)ceilf((xmax + 1.0f) * INV_STEP));
            int y0 = max(0, (int)floorf((1.0f - ymax) * INV_STEP));
            int y1 = min(IMG - 1, (int)ceilf((1.0f - ymin) * INV_STEP));

            if (x0 <= x1 && y0 <= y1) {
                int wdt = x1 - x0 + 1;
                int total = wdt * (y1 - y0 + 1);
                unsigned long long rank = (unsigned long long)layer_rank(ts, l);
                unsigned long long tagbits = (rank << 62)
                    | ((unsigned long long)(1023u - (unsigned)f) << 20)
                    | ((unsigned long long)l << 18);

                for (int i = half * 32 + lane; i < total; i += 64) {
                    int yy = y0 + i / wdt;
                    int xx = x0 + i % wdt;
                    float px = pix_x(xx), py = pix_y(yy);
                    float dx = px - B.x, dy = py - B.y;
                    float l0 = (A.x * dx + A.y * dy) * B.z;
                    float l1 = (A.z * dx + A.w * dy) * B.z;
                    float l2 = 1.0f - l0 - l1;
                    float z  = l0 * B.w + l1 * z1v + l2 * z2v;
                    if (l0 >= 0.0f && l1 >= 0.0f && l2 >= 0.0f && z > EPSF) {
                        float u = l0 * u0 + l1 * u1 + l2 * u2;
                        float v = l0 * v0 + l1 * v1 + l2 * v2;
                        u = fminf(fmaxf(u, 0.0f), 1.0f);
                        v = fminf(fmaxf(v, 0.0f), 1.0f);
                        unsigned txi = (unsigned)(int)rintf(u * 511.0f);
                        unsigned tyi = (unsigned)(int)rintf((1.0f - v) * 511.0f);
                        unsigned long long key = tagbits
                            | ((unsigned long long)(~__float_as_uint(z)) << 30)
                            | ((unsigned long long)tyi << 9)
                            | (unsigned long long)txi;
                        atomicMax(&g_zbuf[yy * IMG + xx], key);
                    }
                }
            }
        }
    }

    // ============ Completion detection: last SHADE_BLOCKS shade ============
    __shared__ int s_slice;
    __syncthreads();
    if (threadIdx.x == 0) {
        __threadfence();                       // release scatter atomics
        unsigned long long v = atomicAdd(&g_fin, 1ull);
        unsigned long long T =
            (v / (unsigned long long)SC_BLOCKS + 1ull) * SC_BLOCKS;
        long long s = (long long)v - (long long)(T - SHADE_BLOCKS);
        s_slice = (int)s;                      // < 0: not a shader
        if (s >= 0) {
            while (true) {
                unsigned long long cur;
                asm volatile("ld.volatile.global.u64 %0, [%1];"
                             : "=l"(cur) : "l"(&g_fin));
                if (cur >= T) break;
                __nanosleep(32);
            }
        }
    }
    __syncthreads();
    int slice = s_slice;
    if (slice < 0) return;
    __threadfence();                           // acquire all scatter atomics

    // ===================== Phase 2: shade (256 pixels/block) ================
    int pid = slice * 256 + threadIdx.x;

    unsigned long long key = g_zbuf[pid];
    g_zbuf[pid] = 0ull;                        // restore empty state

    float c0 = 0.0f, c1 = 0.0f, c2 = 0.0f, hard = 0.0f;
    if (key != 0ull) {
        hard = 1.0f;
        int txi   = (int)(key & 511ull);
        int tyi   = (int)((key >> 9) & 511ull);
        int layer = (int)((key >> 18) & 3ull);
        const float* T2 = tex + layer * 3 * 512 * 512 + tyi * 512 + txi;
        c0 = T2[0];
        c1 = T2[262144];
        c2 = T2[524288];
    }

    out[OFF_IM + pid * 3 + 0] = c0;
    out[OFF_IM + pid * 3 + 1] = c1;
    out[OFF_IM + pid * 3 + 2] = c2;
    out[OFF_PROB + pid] = hard;
    out[OFF_FG + pid]   = hard;
}

// ---------------------------------------------------------------------------
extern "C" void kernel_launch(void* const* d_in, const int* in_sizes, int n_in,
                              void* d_out, int out_size) {
    const float* points = (const float*)d_in[0];
    const float* camrot = (const float*)d_in[1];
    const float* campos = (const float*)d_in[2];
    const float* proj   = (const float*)d_in[3];
    const float* uv     = (const float*)d_in[4];
    const float* tex    = (const float*)d_in[5];
    const float* ts     = (const float*)d_in[6];
    const int*   faces  = (const int*)d_in[7];
    float* out = (float*)d_out;

    render_kernel<<<SC_BLOCKS, 256>>>(points, camrot, campos, proj,
                                      faces, uv, ts, tex, out);
}

// round 14
// speedup vs baseline: 1.2353x; 1.2353x over previous
#include <cuda_runtime.h>
#include <math.h>

#define EPSF 1e-8f
#define NB 3
#define NF 1024
#define NP 768
#define IMG 128
#define NPIX (IMG * IMG)

// out offsets (f32 elements)
#define OFF_IM     0
#define OFF_PROB   49152
#define OFF_NORM   65536
#define OFF_FG     74752

// Combined composite/z buffer, one u64 per pixel. 0 = empty (module-load
// default, restored by shade each call).
// key = rank<<62 | (~bits(z))<<30 | (1023-f)<<20 | layer<<18 | tyi<<9 | txi
//   atomicMax => max composite rank (last-drawn layer in ts order);
//   within a layer: min z, tie -> min face. Texel bits never affect order.
static __device__ unsigned long long g_zbuf[NPIX];

__device__ __forceinline__ float pix_x(int x) {
    const float STEP = 2.0f / 127.0f;
    return (x == 127) ? 1.0f : (-1.0f + x * STEP);
}
__device__ __forceinline__ float pix_y(int y) {
    const float STEP = 2.0f / 127.0f;
    return (y == 127) ? -1.0f : (1.0f - y * STEP);
}

// stable argsort of -ts[:,2] over 3 layers; returns rank of layer l (0..2)
__device__ __forceinline__ int layer_rank(const float* ts, int l) {
    float k0 = -ts[2], k1 = -ts[5], k2 = -ts[8];
    int o0 = 0; float kv = k0;
    if (k1 < kv) { o0 = 1; kv = k1; }
    if (k2 < kv) { o0 = 2; kv = k2; }
    int r0i = (o0 == 0) ? 1 : 0;
    int r1i = (o0 == 2) ? 1 : 2;
    float kr0 = (r0i == 0) ? k0 : k1;
    float kr1 = (r1i == 1) ? k1 : k2;
    int o1, o2;
    if (kr0 <= kr1) { o1 = r0i; o2 = r1i; }
    else            { o1 = r1i; o2 = r0i; }
    return (l == o0) ? 0 : ((l == o1) ? 1 : 2);
}

// ---------------------------------------------------------------------------
// Kernel 1: prep + scatter. TWO warps per (layer, face) — interleaved halves
// of the flattened bbox sweep (halves the big-bbox tail). Identical math to
// the passing R12 kernel. Triggers PDL completion at block end.
// ---------------------------------------------------------------------------
__global__ void __launch_bounds__(256)
scatter_kernel(const float* __restrict__ pts,
               const float* __restrict__ camrot,
               const float* __restrict__ campos,
               const float* __restrict__ proj,
               const int*   __restrict__ faces,
               const float* __restrict__ uv,
               const float* __restrict__ ts,
               float* __restrict__ out_normals) {
    int w = (blockIdx.x * blockDim.x + threadIdx.x) >> 5;   // 0 .. 6143
    int lane = threadIdx.x & 31;
    int wg = w >> 1;            // (layer, face) id
    int half = w & 1;
    int l = wg >> 10;
    int f = wg & (NF - 1);

    int vis[3] = {faces[f * 3 + 0], faces[f * 3 + 1], faces[f * 3 + 2]};
    const float* R = camrot + l * 9;
    const float* C = campos + l * 3;
    float p0 = proj[0], p1 = proj[1];

    float vx[3], vy[3], vz[3], sx[3], sy[3];
#pragma unroll
    for (int k = 0; k < 3; k++) {
        const float* P = pts + (l * NP + vis[k]) * 3;
        float q0 = P[0] - C[0], q1 = P[1] - C[1], q2 = P[2] - C[2];
        float X = R[0] * q0 + R[1] * q1 + R[2] * q2;
        float Y = R[3] * q0 + R[4] * q1 + R[5] * q2;
        float Z = R[6] * q0 + R[7] * q1 + R[8] * q2;
        vx[k] = X; vy[k] = Y; vz[k] = Z;
        float zd = Z + EPSF;
        sx[k] = __fdiv_rn(X * p0, zd);
        sy[k] = __fdiv_rn(Y * p1, zd);
    }

    if (half == 0 && lane == 0) {
        float e1xx = vx[1] - vx[0], e1yy = vy[1] - vy[0], e1zz = vz[1] - vz[0];
        float e2xx = vx[2] - vx[0], e2yy = vy[2] - vy[0], e2zz = vz[2] - vz[0];
        float nx = e1yy * e2zz - e1zz * e2yy;
        float ny = e1zz * e2xx - e1xx * e2zz;
        float nz = e1xx * e2yy - e1yy * e2xx;
        float nn = __fsqrt_rn(nx * nx + ny * ny + nz * nz) + EPSF;
        float* on = out_normals + wg * 3;
        on[0] = __fdiv_rn(nx, nn);
        on[1] = __fdiv_rn(ny, nn);
        on[2] = __fdiv_rn(nz, nn);
    }

    float ax = sx[0], ay = sy[0], bx = sx[1], by = sy[1], cx = sx[2], cy = sy[2];
    float d = (by - cy) * (ax - cx) + (cx - bx) * (ay - cy);
    float zmax = fmaxf(vz[0], fmaxf(vz[1], vz[2]));
    bool valid = (fabsf(d) > EPSF) && (zmax > EPSF);

    if (valid) {
        float dn = d + EPSF;
        float rd = __frcp_rn(dn);
        float4 A = make_float4(by - cy, cx - bx, cy - ay, ax - cx);
        float4 B = make_float4(cx, cy, rd, vz[0]);
        float z1v = vz[1], z2v = vz[2];

        const float* U = uv + l * NP * 2;
        float u0 = U[2 * vis[0]],     u1 = U[2 * vis[1]],     u2 = U[2 * vis[2]];
        float v0 = U[2 * vis[0] + 1], v1 = U[2 * vis[1] + 1], v2 = U[2 * vis[2] + 1];

        const float STEP = 2.0f / 127.0f;
        float pad = 1.0f * STEP;
        float xmin = fminf(ax, fminf(bx, cx)) - pad;
        float xmax = fmaxf(ax, fmaxf(bx, cx)) + pad;
        float ymin = fminf(ay, fminf(by, cy)) - pad;
        float ymax = fmaxf(ay, fmaxf(by, cy)) + pad;

        const float INV_STEP = 63.5f;   // 1 / (2/127)
        int x0 = max(0, (int)floorf((xmin + 1.0f) * INV_STEP));
        int x1 = min(IMG - 1, (int)ceilf((xmax + 1.0f) * INV_STEP));
        int y0 = max(0, (int)floorf((1.0f - ymax) * INV_STEP));
        int y1 = min(IMG - 1, (int)ceilf((1.0f - ymin) * INV_STEP));

        if (x0 <= x1 && y0 <= y1) {
            int wdt = x1 - x0 + 1;
            int total = wdt * (y1 - y0 + 1);
            unsigned long long rank = (unsigned long long)layer_rank(ts, l);
            unsigned long long tagbits = (rank << 62)
                | ((unsigned long long)(1023u - (unsigned)f) << 20)
                | ((unsigned long long)l << 18);

            for (int i = half * 32 + lane; i < total; i += 64) {
                int yy = y0 + i / wdt;
                int xx = x0 + i % wdt;
                float px = pix_x(xx), py = pix_y(yy);
                float dx = px - B.x, dy = py - B.y;
                float l0 = (A.x * dx + A.y * dy) * B.z;
                float l1 = (A.z * dx + A.w * dy) * B.z;
                float l2 = 1.0f - l0 - l1;
                float z  = l0 * B.w + l1 * z1v + l2 * z2v;
                if (l0 >= 0.0f && l1 >= 0.0f && l2 >= 0.0f && z > EPSF) {
                    float u = l0 * u0 + l1 * u1 + l2 * u2;
                    float v = l0 * v0 + l1 * v1 + l2 * v2;
                    u = fminf(fmaxf(u, 0.0f), 1.0f);
                    v = fminf(fmaxf(v, 0.0f), 1.0f);
                    unsigned txi = (unsigned)(int)rintf(u * 511.0f);
                    unsigned tyi = (unsigned)(int)rintf((1.0f - v) * 511.0f);
                    unsigned long long key = tagbits
                        | ((unsigned long long)(~__float_as_uint(z)) << 30)
                        | ((unsigned long long)tyi << 9)
                        | (unsigned long long)txi;
                    atomicMax(&g_zbuf[yy * IMG + xx], key);
                }
            }
        }
    }

    // PDL: signal that dependent (shade) may complete its launch.
    cudaTriggerProgrammaticLaunchCompletion();
}

// ---------------------------------------------------------------------------
// Kernel 2: shade. Launched with programmatic stream serialization so its
// launch/ramp overlaps scatter; cudaGridDependencySynchronize() provides the
// producer->consumer ordering before any zbuf read. One thread per
// (pixel, channel); identical math/layout to the passing R12 kernel.
// ---------------------------------------------------------------------------
__global__ void __launch_bounds__(256)
shade_kernel(const float* __restrict__ tex,
             float* __restrict__ out) {
    int tid = blockIdx.x * blockDim.x + threadIdx.x;
    int pid = tid / 3;
    int ch  = tid - pid * 3;

    cudaGridDependencySynchronize();    // wait for scatter completion

    if (tid >= NPIX * 3) return;

    unsigned long long key = g_zbuf[pid];

    float c = 0.0f, hard = 0.0f;
    if (key != 0ull) {
        hard = 1.0f;
        int txi   = (int)(key & 511ull);
        int tyi   = (int)((key >> 9) & 511ull);
        int layer = (int)((key >> 18) & 3ull);
        c = tex[layer * 3 * 512 * 512 + ch * 262144 + tyi * 512 + txi];
    }

    out[OFF_IM + tid] = c;                     // == out[OFF_IM + pid*3 + ch]
    if (ch == 0) out[OFF_PROB + pid] = hard;
    else if (ch == 1) out[OFF_FG + pid] = hard;
    else g_zbuf[pid] = 0ull;                   // restore empty state
}

// ---------------------------------------------------------------------------
extern "C" void kernel_launch(void* const* d_in, const int* in_sizes, int n_in,
                              void* d_out, int out_size) {
    const float* points = (const float*)d_in[0];
    const float* camrot = (const float*)d_in[1];
    const float* campos = (const float*)d_in[2];
    const float* proj   = (const float*)d_in[3];
    const float* uv     = (const float*)d_in[4];
    const float* tex    = (const float*)d_in[5];
    const float* ts     = (const float*)d_in[6];
    const int*   faces  = (const int*)d_in[7];
    float* out = (float*)d_out;

    // 6144 warps (2 per (layer,face)) = 768 blocks of 8 warps
    scatter_kernel<<<(NB * NF * 2 * 32) / 256, 256>>>(points, camrot, campos,
                                                      proj, faces, uv, ts,
                                                      out + OFF_NORM);

    // shade with Programmatic Dependent Launch: overlap launch/ramp with
    // scatter; ordering enforced by cudaGridDependencySynchronize() inside.
    cudaLaunchConfig_t cfg = {};
    cfg.gridDim  = dim3((NPIX * 3 + 255) / 256);
    cfg.blockDim = dim3(256);
    cudaLaunchAttribute attrs[1];
    attrs[0].id = cudaLaunchAttributeProgrammaticStreamSerialization;
    attrs[0].val.programmaticStreamSerializationAllowed = 1;
    cfg.attrs = attrs;
    cfg.numAttrs = 1;
    cudaLaunchKernelEx(&cfg, shade_kernel, tex, out);
}

// round 15
// speedup vs baseline: 1.2600x; 1.0200x over previous
#include <cuda_runtime.h>
#include <math.h>

#define EPSF 1e-8f
#define NB 3
#define NF 1024
#define NP 768
#define IMG 128
#define NPIX (IMG * IMG)

// out offsets (f32 elements)
#define OFF_IM     0
#define OFF_PROB   49152
#define OFF_NORM   65536
#define OFF_FG     74752

// Combined composite/z buffer, one u64 per pixel. 0 = empty (module-load
// default, restored by shade each call).
// key = rank<<62 | (~bits(z))<<30 | (1023-f)<<20 | layer<<18 | tyi<<9 | txi
static __device__ unsigned long long g_zbuf[NPIX];

__device__ __forceinline__ float pix_x(int x) {
    const float STEP = 2.0f / 127.0f;
    return (x == 127) ? 1.0f : (-1.0f + x * STEP);
}
__device__ __forceinline__ float pix_y(int y) {
    const float STEP = 2.0f / 127.0f;
    return (y == 127) ? -1.0f : (1.0f - y * STEP);
}

// stable argsort of -ts[:,2] over 3 layers; returns rank of layer l (0..2)
__device__ __forceinline__ int layer_rank(const float* ts, int l) {
    float k0 = -ts[2], k1 = -ts[5], k2 = -ts[8];
    int o0 = 0; float kv = k0;
    if (k1 < kv) { o0 = 1; kv = k1; }
    if (k2 < kv) { o0 = 2; kv = k2; }
    int r0i = (o0 == 0) ? 1 : 0;
    int r1i = (o0 == 2) ? 1 : 2;
    float kr0 = (r0i == 0) ? k0 : k1;
    float kr1 = (r1i == 1) ? k1 : k2;
    int o1, o2;
    if (kr0 <= kr1) { o1 = r0i; o2 = r1i; }
    else            { o1 = r1i; o2 = r0i; }
    return (l == o0) ? 0 : ((l == o1) ? 1 : 2);
}

// ---------------------------------------------------------------------------
// Kernel 1: prep + scatter. Two warps per (layer,face), interleaved halves of
// the flattened bbox sweep. ALL prep (transforms/normals/bbox/uv) happens
// BEFORE cudaGridDependencySynchronize(), so under PDL it overlaps the
// previous replay's shade; only the zbuf atomicMax sweep waits.
// ---------------------------------------------------------------------------
__global__ void __launch_bounds__(256)
scatter_kernel(const float* __restrict__ pts,
               const float* __restrict__ camrot,
               const float* __restrict__ campos,
               const float* __restrict__ proj,
               const int*   __restrict__ faces,
               const float* __restrict__ uv,
               const float* __restrict__ ts,
               float* __restrict__ out_normals) {
    int w = (blockIdx.x * blockDim.x + threadIdx.x) >> 5;   // 0 .. 6143
    int lane = threadIdx.x & 31;
    int wg = w >> 1;            // (layer, face) id
    int half = w & 1;
    int l = wg >> 10;
    int f = wg & (NF - 1);

    // ---------------- pre-sync phase (overlaps previous shade) -------------
    int vis[3] = {faces[f * 3 + 0], faces[f * 3 + 1], faces[f * 3 + 2]};
    const float* R = camrot + l * 9;
    const float* C = campos + l * 3;
    float p0 = proj[0], p1 = proj[1];

    float vx[3], vy[3], vz[3], sx[3], sy[3];
#pragma unroll
    for (int k = 0; k < 3; k++) {
        const float* P = pts + (l * NP + vis[k]) * 3;
        float q0 = P[0] - C[0], q1 = P[1] - C[1], q2 = P[2] - C[2];
        float X = R[0] * q0 + R[1] * q1 + R[2] * q2;
        float Y = R[3] * q0 + R[4] * q1 + R[5] * q2;
        float Z = R[6] * q0 + R[7] * q1 + R[8] * q2;
        vx[k] = X; vy[k] = Y; vz[k] = Z;
        float zd = Z + EPSF;
        sx[k] = __fdiv_rn(X * p0, zd);
        sy[k] = __fdiv_rn(Y * p1, zd);
    }

    if (half == 0 && lane == 0) {
        float e1xx = vx[1] - vx[0], e1yy = vy[1] - vy[0], e1zz = vz[1] - vz[0];
        float e2xx = vx[2] - vx[0], e2yy = vy[2] - vy[0], e2zz = vz[2] - vz[0];
        float nx = e1yy * e2zz - e1zz * e2yy;
        float ny = e1zz * e2xx - e1xx * e2zz;
        float nz = e1xx * e2yy - e1yy * e2xx;
        float nn = __fsqrt_rn(nx * nx + ny * ny + nz * nz) + EPSF;
        float* on = out_normals + wg * 3;
        on[0] = __fdiv_rn(nx, nn);
        on[1] = __fdiv_rn(ny, nn);
        on[2] = __fdiv_rn(nz, nn);
    }

    float ax = sx[0], ay = sy[0], bx = sx[1], by = sy[1], cx = sx[2], cy = sy[2];
    float d = (by - cy) * (ax - cx) + (cx - bx) * (ay - cy);
    float zmax = fmaxf(vz[0], fmaxf(vz[1], vz[2]));
    bool valid = (fabsf(d) > EPSF) && (zmax > EPSF);

    float dn = d + EPSF;
    float rd = __frcp_rn(dn);
    float4 A = make_float4(by - cy, cx - bx, cy - ay, ax - cx);
    float4 B = make_float4(cx, cy, rd, vz[0]);
    float z1v = vz[1], z2v = vz[2];

    const float* U = uv + l * NP * 2;
    float u0 = U[2 * vis[0]],     u1 = U[2 * vis[1]],     u2 = U[2 * vis[2]];
    float v0 = U[2 * vis[0] + 1], v1 = U[2 * vis[1] + 1], v2 = U[2 * vis[2] + 1];

    const float STEP = 2.0f / 127.0f;
    float pad = 0.25f * STEP;   // FP noise scale ~1e-6 NDC; 3.9e-3 is safe
    float xmin = fminf(ax, fminf(bx, cx)) - pad;
    float xmax = fmaxf(ax, fmaxf(bx, cx)) + pad;
    float ymin = fminf(ay, fminf(by, cy)) - pad;
    float ymax = fmaxf(ay, fmaxf(by, cy)) + pad;

    const float INV_STEP = 63.5f;   // 1 / (2/127)
    int x0 = max(0, (int)floorf((xmin + 1.0f) * INV_STEP));
    int x1 = min(IMG - 1, (int)ceilf((xmax + 1.0f) * INV_STEP));
    int y0 = max(0, (int)floorf((1.0f - ymax) * INV_STEP));
    int y1 = min(IMG - 1, (int)ceilf((1.0f - ymin) * INV_STEP));

    unsigned long long rank = (unsigned long long)layer_rank(ts, l);
    unsigned long long tagbits = (rank << 62)
        | ((unsigned long long)(1023u - (unsigned)f) << 20)
        | ((unsigned long long)l << 18);

    // ------------- sync: previous shade's zbuf reset must be visible -------
    cudaGridDependencySynchronize();

    if (valid && x0 <= x1 && y0 <= y1) {
        int wdt = x1 - x0 + 1;
        int total = wdt * (y1 - y0 + 1);
        for (int i = half * 32 + lane; i < total; i += 64) {
            int yy = y0 + i / wdt;
            int xx = x0 + i % wdt;
            float px = pix_x(xx), py = pix_y(yy);
            float dx = px - B.x, dy = py - B.y;
            float l0 = (A.x * dx + A.y * dy) * B.z;
            float l1 = (A.z * dx + A.w * dy) * B.z;
            float l2 = 1.0f - l0 - l1;
            float z  = l0 * B.w + l1 * z1v + l2 * z2v;
            if (l0 >= 0.0f && l1 >= 0.0f && l2 >= 0.0f && z > EPSF) {
                float u = l0 * u0 + l1 * u1 + l2 * u2;
                float v = l0 * v0 + l1 * v1 + l2 * v2;
                u = fminf(fmaxf(u, 0.0f), 1.0f);
                v = fminf(fmaxf(v, 0.0f), 1.0f);
                unsigned txi = (unsigned)(int)rintf(u * 511.0f);
                unsigned tyi = (unsigned)(int)rintf((1.0f - v) * 511.0f);
                unsigned long long key = tagbits
                    | ((unsigned long long)(~__float_as_uint(z)) << 30)
                    | ((unsigned long long)tyi << 9)
                    | (unsigned long long)txi;
                atomicMax(&g_zbuf[yy * IMG + xx], key);
            }
        }
    }

    cudaTriggerProgrammaticLaunchCompletion();
}

// ---------------------------------------------------------------------------
// Kernel 2: shade. One thread per (pixel, channel). Sync sits immediately
// before the first zbuf read; trigger fires after the zbuf reset so the next
// replay's scatter can start its pre-sync prep early.
// ---------------------------------------------------------------------------
__global__ void __launch_bounds__(256)
shade_kernel(const float* __restrict__ tex,
             float* __restrict__ out) {
    int tid = blockIdx.x * blockDim.x + threadIdx.x;
    int pid = tid / 3;
    int ch  = tid - pid * 3;
    bool active = (tid < NPIX * 3);

    cudaGridDependencySynchronize();    // wait for scatter completion

    if (active) {
        unsigned long long key = g_zbuf[pid];

        float c = 0.0f, hard = 0.0f;
        if (key != 0ull) {
            hard = 1.0f;
            int txi   = (int)(key & 511ull);
            int tyi   = (int)((key >> 9) & 511ull);
            int layer = (int)((key >> 18) & 3ull);
            c = tex[layer * 3 * 512 * 512 + ch * 262144 + tyi * 512 + txi];
        }

        out[OFF_IM + tid] = c;                 // == out[OFF_IM + pid*3 + ch]
        if (ch == 0) out[OFF_PROB + pid] = hard;
        else if (ch == 1) out[OFF_FG + pid] = hard;
        else g_zbuf[pid] = 0ull;               // restore empty state
    }

    cudaTriggerProgrammaticLaunchCompletion();
}

// ---------------------------------------------------------------------------
extern "C" void kernel_launch(void* const* d_in, const int* in_sizes, int n_in,
                              void* d_out, int out_size) {
    const float* points = (const float*)d_in[0];
    const float* camrot = (const float*)d_in[1];
    const float* campos = (const float*)d_in[2];
    const float* proj   = (const float*)d_in[3];
    const float* uv     = (const float*)d_in[4];
    const float* tex    = (const float*)d_in[5];
    const float* ts     = (const float*)d_in[6];
    const int*   faces  = (const int*)d_in[7];
    float* out = (float*)d_out;

    cudaLaunchAttribute attrs[1];
    attrs[0].id = cudaLaunchAttributeProgrammaticStreamSerialization;
    attrs[0].val.programmaticStreamSerializationAllowed = 1;

    // scatter: 6144 warps (2 per (layer,face)) = 768 blocks of 8 warps
    {
        cudaLaunchConfig_t cfg = {};
        cfg.gridDim  = dim3((NB * NF * 2 * 32) / 256);
        cfg.blockDim = dim3(256);
        cfg.attrs = attrs;
        cfg.numAttrs = 1;
        cudaLaunchKernelEx(&cfg, scatter_kernel, points, camrot, campos, proj,
                           faces, uv, ts, out + OFF_NORM);
    }
    // shade
    {
        cudaLaunchConfig_t cfg = {};
        cfg.gridDim  = dim3((NPIX * 3 + 255) / 256);
        cfg.blockDim = dim3(256);
        cfg.attrs = attrs;
        cfg.numAttrs = 1;
        cudaLaunchKernelEx(&cfg, shade_kernel, tex, out);
    }
}